// round 10
// baseline (speedup 1.0000x reference)
#include <cuda_runtime.h>

#define NB   2
#define CCH  128
#define HH   64
#define WWD  64
#define HW   (HH*WWD)
#define NPIX (NB*HW)

#define T1PX 32     // pixels per block, proj
#define TILE 32     // pixels per block, attn
#define LWIN 9
#define KK   81
#define PML  9      // pmat row stride (coprime with 32)

// scratch
__device__ float g_G[CCH*CCH];     // G = W^T W
__device__ float g_qt[NPIX*CCH];   // qg = G @ fk, pixel-major [p][c]
__device__ float g_ftt[NPIX*CCH];  // ft transposed, pixel-major [p][c]

typedef unsigned long long ull;

__device__ __forceinline__ ull pack2(float x, float y) {
    ull r;
    asm("mov.b64 %0, {%1, %2};" : "=l"(r) : "f"(x), "f"(y));
    return r;
}
__device__ __forceinline__ ull fma2(ull a, ull b, ull c) {
    ull d;
    asm("fma.rn.f32x2 %0, %1, %2, %3;" : "=l"(d) : "l"(a), "l"(b), "l"(c));
    return d;
}
__device__ __forceinline__ float2 unpack2(ull p) {
    float x, y;
    asm("mov.b64 {%0, %1}, %2;" : "=f"(x), "=f"(y) : "l"(p));
    return make_float2(x, y);
}

// ---------------------------------------------------------------------------
// Kernel 0: G = W^T W.  128 blocks x 128 thr, 4 independent acc chains for
// MLP>=8 (the R7 version was a single serial chain = latency-bound).
// ---------------------------------------------------------------------------
__global__ void __launch_bounds__(128) gemmG_kernel(const float* __restrict__ Wm)
{
    const int a = blockIdx.x;
    const int b = threadIdx.x;
    float a0 = 0.f, a1 = 0.f, a2 = 0.f, a3 = 0.f;
#pragma unroll 4
    for (int o = 0; o < 32; o++) {
        a0 += Wm[(o      )*CCH + a] * Wm[(o      )*CCH + b];
        a1 += Wm[(o +  32)*CCH + a] * Wm[(o +  32)*CCH + b];
        a2 += Wm[(o +  64)*CCH + a] * Wm[(o +  64)*CCH + b];
        a3 += Wm[(o +  96)*CCH + a] * Wm[(o +  96)*CCH + b];
    }
    g_G[a*CCH + b] = (a0 + a1) + (a2 + a3);
}

// ---------------------------------------------------------------------------
// Kernel 1: qg = G @ fk (pixel-major out) + transpose of ft.
// 128 thr, 32 px/block, 256 blocks. Thread tile 8o x 4px, f32x2 acc.
// ---------------------------------------------------------------------------
__global__ void __launch_bounds__(128) proj_kernel(
    const float* __restrict__ ft, const float* __restrict__ fk)
{
    extern __shared__ float sm[];
    float* sB = sm;                  // [128][36] fk tile
    float* sF = sB + CCH*36;         // [128][36] ft tile
    float* sS = sF + CCH*36;         // [32][129] staging

    const int t  = threadIdx.x;
    const int p0 = blockIdx.x * T1PX;
    const int n  = p0 / HW;
    const int pp = p0 - n * HW;
    const float* fta = ft + n*CCH*HW + pp;
    const float* fka = fk + n*CCH*HW + pp;

    for (int j = t; j < CCH*T1PX; j += 128) {
        int i = j >> 5, px = j & 31;
        sB[i*36 + px] = fka[i*HW + px];
        sF[i*36 + px] = fta[i*HW + px];
    }
    __syncthreads();

    const int px4 = (t & 7) * 4;     // 8 groups of 4 px
    const int o0  = (t >> 3) * 8;    // 16 groups of 8 output channels

    ull aQ[8][2];
#pragma unroll
    for (int oo = 0; oo < 8; oo++) aQ[oo][0] = aQ[oo][1] = 0ull;

    for (int i = 0; i < CCH; i += 4) {
        float4 g4[8];
#pragma unroll
        for (int oo = 0; oo < 8; oo++)
            g4[oo] = *(const float4*)&g_G[(o0+oo)*CCH + i];
#pragma unroll
        for (int ii = 0; ii < 4; ii++) {
            float4 b = *(const float4*)&sB[(i+ii)*36 + px4];
            ull b01 = pack2(b.x, b.y), b23 = pack2(b.z, b.w);
#pragma unroll
            for (int oo = 0; oo < 8; oo++) {
                float w = (ii == 0) ? g4[oo].x : (ii == 1) ? g4[oo].y
                        : (ii == 2) ? g4[oo].z : g4[oo].w;
                ull ww = pack2(w, w);
                aQ[oo][0] = fma2(b01, ww, aQ[oo][0]);
                aQ[oo][1] = fma2(b23, ww, aQ[oo][1]);
            }
        }
    }

#pragma unroll
    for (int oo = 0; oo < 8; oo++) {
        float2 v0 = unpack2(aQ[oo][0]);
        float2 v1 = unpack2(aQ[oo][1]);
        sS[(px4+0)*129 + o0+oo] = v0.x;
        sS[(px4+1)*129 + o0+oo] = v0.y;
        sS[(px4+2)*129 + o0+oo] = v1.x;
        sS[(px4+3)*129 + o0+oo] = v1.y;
    }
    __syncthreads();
    float* gq = g_qt + p0*CCH;
    for (int j = t; j < T1PX*CCH; j += 128)
        gq[j] = sS[(j>>7)*129 + (j & 127)];

    float* gf = g_ftt + p0*CCH;
    for (int j = t; j < T1PX*CCH; j += 128) {
        int px = j >> 7, c = j & 127;
        gf[j] = sF[c*36 + px];
    }
}

// ---------------------------------------------------------------------------
// Kernel 2: local attention, SMEM-FREE windows. Each warp owns 4 px, loads
// its 12 window vectors per di straight from L2/L1 (g_ftt). Warps fully
// independent; only 2 block barriers (output transpose). 256 thr, 256 blocks.
// ---------------------------------------------------------------------------
__global__ void __launch_bounds__(256) attn_kernel(float* __restrict__ out)
{
    __shared__ float simw[TILE*KK];       // [32][81]
    __shared__ float pmat[8*36*PML];      // per-warp [36][9]
    __shared__ float sout[TILE*132];      // output staging

    const int t = threadIdx.x, lane = t & 31, w = t >> 5;
    const int x0 = blockIdx.x * TILE;
    const int y  = blockIdx.y;
    const int n  = blockIdx.z;
    const int pb = w * 4;
    const int c4 = lane * 4;

    float* pmw = pmat + w * 36*PML;
    const int vu  = lane / 9;             // lane -> value v = u*9+dj (v<32)
    const int vdj = lane - vu*9;
    float* simw_main = simw + (pb + vu)*KK + vdj;
    float* simw_tail = simw + (pb + 3)*KK + 5 + lane;   // v 32..35, lane<4

    const float* base = g_ftt + (size_t)n*HW*CCH;

    // query (= G@fk) vectors, packed
    ull q01[4], q23[4];
#pragma unroll
    for (int u = 0; u < 4; u++) {
        float4 q = *(const float4*)&g_qt[((n*HH + y)*WWD + x0 + pb + u)*CCH + c4];
        q01[u] = pack2(q.x, q.y);
        q23[u] = pack2(q.z, q.w);
    }

    // ================= Phase A: sim = qg . ft windows =================
#pragma unroll 1
    for (int di = 0; di < LWIN; di++) {
        const int gy = y + di - 4;
        if ((unsigned)gy < (unsigned)HH) {
            const float* rowp = base + ((size_t)gy*WWD)*CCH + c4;
#pragma unroll
            for (int jj = 0; jj < 12; jj++) {
                const int gx = x0 + pb - 4 + jj;     // warp-uniform
                float4 k4 = make_float4(0.f, 0.f, 0.f, 0.f);
                if ((unsigned)gx < (unsigned)WWD)
                    k4 = *(const float4*)&rowp[(size_t)gx*CCH];
                ull k01 = pack2(k4.x, k4.y), k23 = pack2(k4.z, k4.w);
#pragma unroll
                for (int u = 0; u < 4; u++) {
                    int dj = jj - u;
                    if (dj >= 0 && dj < 9) {
                        ull tt = fma2(q01[u], k01, 0ull);
                        tt = fma2(q23[u], k23, tt);
                        float2 p = unpack2(tt);
                        float v = p.x + p.y;
                        v += __shfl_xor_sync(0xffffffffu, v, 16);
                        v += __shfl_xor_sync(0xffffffffu, v, 8);
                        if (lane < 8) pmw[(u*9 + dj)*PML + lane] = v;
                    }
                }
            }
            __syncwarp();
            {   // final reduce: lane sums row 'lane' (stride 9, conflict-free)
                const float* r = pmw + lane*PML;
                simw_main[di*LWIN] =
                    ((r[0]+r[1]) + (r[2]+r[3])) + ((r[4]+r[5]) + (r[6]+r[7]));
                if (lane < 4) {
                    const float* r2 = pmw + (32 + lane)*PML;
                    simw_tail[di*LWIN] =
                        ((r2[0]+r2[1]) + (r2[2]+r2[3])) + ((r2[4]+r2[5]) + (r2[6]+r2[7]));
                }
            }
            __syncwarp();
        } else {
            simw_main[di*LWIN] = 0.f;
            if (lane < 4) simw_tail[di*LWIN] = 0.f;
        }
    }
    __syncwarp();

    // ================= Phase B: softmax over 81 (own rows only) ============
#pragma unroll 1
    for (int u = 0; u < 4; u++) {
        float* srow = simw + (pb + u)*KK;
        float v0 = srow[lane];
        float v1 = srow[32 + lane];
        float v2 = (lane < 17) ? srow[64 + lane] : -1e30f;
        float m = fmaxf(fmaxf(v0, v1), v2);
        m = fmaxf(m, __shfl_xor_sync(0xffffffffu, m, 16));
        m = fmaxf(m, __shfl_xor_sync(0xffffffffu, m, 8));
        m = fmaxf(m, __shfl_xor_sync(0xffffffffu, m, 4));
        m = fmaxf(m, __shfl_xor_sync(0xffffffffu, m, 2));
        m = fmaxf(m, __shfl_xor_sync(0xffffffffu, m, 1));
        float e0 = __expf(v0 - m);
        float e1 = __expf(v1 - m);
        float e2 = (lane < 17) ? __expf(v2 - m) : 0.f;
        float s = e0 + e1 + e2;
        s += __shfl_xor_sync(0xffffffffu, s, 16);
        s += __shfl_xor_sync(0xffffffffu, s, 8);
        s += __shfl_xor_sync(0xffffffffu, s, 4);
        s += __shfl_xor_sync(0xffffffffu, s, 2);
        s += __shfl_xor_sync(0xffffffffu, s, 1);
        float inv = 1.0f / s;
        srow[lane]      = e0 * inv;
        srow[32 + lane] = e1 * inv;
        if (lane < 17) srow[64 + lane] = e2 * inv;
    }
    __syncwarp();

    // ================= Phase C: out = ft windows @ weights =================
    ull o01[4], o23[4];
#pragma unroll
    for (int u = 0; u < 4; u++) { o01[u] = 0ull; o23[u] = 0ull; }

#pragma unroll 1
    for (int di = 0; di < LWIN; di++) {
        const int gy = y + di - 4;
        if ((unsigned)gy >= (unsigned)HH) continue;
        const float* rowp = base + ((size_t)gy*WWD)*CCH + c4;
#pragma unroll
        for (int jj = 0; jj < 12; jj++) {
            const int gx = x0 + pb - 4 + jj;
            float4 f4 = make_float4(0.f, 0.f, 0.f, 0.f);
            if ((unsigned)gx < (unsigned)WWD)
                f4 = *(const float4*)&rowp[(size_t)gx*CCH];
            ull f01 = pack2(f4.x, f4.y), f23 = pack2(f4.z, f4.w);
#pragma unroll
            for (int u = 0; u < 4; u++) {
                int dj = jj - u;
                if (dj >= 0 && dj < 9) {
                    float wv = simw[(pb + u)*KK + di*LWIN + dj];  // broadcast
                    ull ww = pack2(wv, wv);
                    o01[u] = fma2(f01, ww, o01[u]);
                    o23[u] = fma2(f23, ww, o23[u]);
                }
            }
        }
    }

    // output staging + coalesced (n,c,h,w) store
#pragma unroll
    for (int u = 0; u < 4; u++) {
        float2 a = unpack2(o01[u]);
        float2 b = unpack2(o23[u]);
        *(float4*)&sout[(pb+u)*132 + c4] = make_float4(a.x, a.y, b.x, b.y);
    }
    __syncthreads();

    float* ob = out + (n*CCH*HH + y)*WWD + x0;
    for (int j = t; j < CCH*TILE; j += 256) {
        int c = j >> 5, px = j & 31;
        ob[c*HW + px] = sout[px*132 + c];
    }
}

// ---------------------------------------------------------------------------
extern "C" void kernel_launch(void* const* d_in, const int* in_sizes, int n_in,
                              void* d_out, int out_size)
{
    (void)in_sizes; (void)n_in; (void)out_size;
    const float* ft = (const float*)d_in[0];
    const float* fk = (const float*)d_in[1];
    const float* Wm = (const float*)d_in[2];
    float* out = (float*)d_out;

    const size_t smem1 = (2*CCH*36 + T1PX*129) * sizeof(float);  // ~53.4 KB
    cudaFuncSetAttribute(proj_kernel, cudaFuncAttributeMaxDynamicSharedMemorySize,
                         (int)smem1);

    gemmG_kernel<<<CCH, CCH>>>(Wm);
    proj_kernel<<<NPIX / T1PX, 128, smem1>>>(ft, fk);

    dim3 g2(WWD / TILE, HH, NB);
    attn_kernel<<<g2, 256>>>(out);
}

// round 12
// speedup vs baseline: 1.2181x; 1.2181x over previous
#include <cuda_runtime.h>

#define NB   2
#define CCH  128
#define HH   64
#define WWD  64
#define HW   (HH*WWD)
#define NPIX (NB*HW)

#define T1PX 32     // pixels per block, proj
#define TILE 16     // pixels per block, attn
#define LWIN 9
#define KK   81
#define PML  9      // pmat row stride (coprime with 32)
#define NV   18     // values per warp per di (2 px x 9 dj)

// scratch
__device__ float g_G[CCH*CCH];     // G = W^T W
__device__ float g_qt[NPIX*CCH];   // qg = G @ fk, pixel-major [p][c]
__device__ float g_ftt[NPIX*CCH];  // ft transposed, pixel-major [p][c]

typedef unsigned long long ull;

__device__ __forceinline__ ull pack2(float x, float y) {
    ull r;
    asm("mov.b64 %0, {%1, %2};" : "=l"(r) : "f"(x), "f"(y));
    return r;
}
__device__ __forceinline__ ull fma2(ull a, ull b, ull c) {
    ull d;
    asm("fma.rn.f32x2 %0, %1, %2, %3;" : "=l"(d) : "l"(a), "l"(b), "l"(c));
    return d;
}
__device__ __forceinline__ float2 unpack2(ull p) {
    float x, y;
    asm("mov.b64 {%0, %1}, %2;" : "=f"(x), "=f"(y) : "l"(p));
    return make_float2(x, y);
}

// ---------------------------------------------------------------------------
// Kernel 0: G = W^T W.  128 blocks x 128 thr. a-column staged in smem
// (removes the uniform-load chain), o-loop FULLY unrolled with 8 chains and
// max-reg budget so ptxas batches the coalesced b-loads (MLP >= 30).
// ---------------------------------------------------------------------------
__global__ void __launch_bounds__(128, 1) gemmG_kernel(const float* __restrict__ Wm)
{
    __shared__ float sWa[CCH];
    const int a = blockIdx.x;
    const int b = threadIdx.x;

    sWa[b] = Wm[b*CCH + a];          // column a (one element per thread)
    __syncthreads();

    float acc[8];
#pragma unroll
    for (int j = 0; j < 8; j++) acc[j] = 0.f;

#pragma unroll
    for (int o = 0; o < CCH; o++)
        acc[o & 7] += sWa[o] * Wm[o*CCH + b];

    g_G[a*CCH + b] = ((acc[0]+acc[1]) + (acc[2]+acc[3]))
                   + ((acc[4]+acc[5]) + (acc[6]+acc[7]));
}

// ---------------------------------------------------------------------------
// Kernel 1: qg = G @ fk (pixel-major out) + transpose of ft.
// 128 thr, 32 px/block, 256 blocks. Thread tile 8o x 4px, f32x2 acc.
// ---------------------------------------------------------------------------
__global__ void __launch_bounds__(128) proj_kernel(
    const float* __restrict__ ft, const float* __restrict__ fk)
{
    extern __shared__ float sm[];
    float* sB = sm;                  // [128][36] fk tile
    float* sF = sB + CCH*36;         // [128][36] ft tile
    float* sS = sF + CCH*36;         // [32][129] staging

    const int t  = threadIdx.x;
    const int p0 = blockIdx.x * T1PX;
    const int n  = p0 / HW;
    const int pp = p0 - n * HW;
    const float* fta = ft + n*CCH*HW + pp;
    const float* fka = fk + n*CCH*HW + pp;

    for (int j = t; j < CCH*T1PX; j += 128) {
        int i = j >> 5, px = j & 31;
        sB[i*36 + px] = fka[i*HW + px];
        sF[i*36 + px] = fta[i*HW + px];
    }
    __syncthreads();

    const int px4 = (t & 7) * 4;     // 8 groups of 4 px
    const int o0  = (t >> 3) * 8;    // 16 groups of 8 output channels

    ull aQ[8][2];
#pragma unroll
    for (int oo = 0; oo < 8; oo++) aQ[oo][0] = aQ[oo][1] = 0ull;

    for (int i = 0; i < CCH; i += 4) {
        float4 g4[8];
#pragma unroll
        for (int oo = 0; oo < 8; oo++)
            g4[oo] = *(const float4*)&g_G[(o0+oo)*CCH + i];
#pragma unroll
        for (int ii = 0; ii < 4; ii++) {
            float4 b = *(const float4*)&sB[(i+ii)*36 + px4];
            ull b01 = pack2(b.x, b.y), b23 = pack2(b.z, b.w);
#pragma unroll
            for (int oo = 0; oo < 8; oo++) {
                float w = (ii == 0) ? g4[oo].x : (ii == 1) ? g4[oo].y
                        : (ii == 2) ? g4[oo].z : g4[oo].w;
                ull ww = pack2(w, w);
                aQ[oo][0] = fma2(b01, ww, aQ[oo][0]);
                aQ[oo][1] = fma2(b23, ww, aQ[oo][1]);
            }
        }
    }

#pragma unroll
    for (int oo = 0; oo < 8; oo++) {
        float2 v0 = unpack2(aQ[oo][0]);
        float2 v1 = unpack2(aQ[oo][1]);
        sS[(px4+0)*129 + o0+oo] = v0.x;
        sS[(px4+1)*129 + o0+oo] = v0.y;
        sS[(px4+2)*129 + o0+oo] = v1.x;
        sS[(px4+3)*129 + o0+oo] = v1.y;
    }
    __syncthreads();
    float* gq = g_qt + p0*CCH;
    for (int j = t; j < T1PX*CCH; j += 128)
        gq[j] = sS[(j>>7)*129 + (j & 127)];

    float* gf = g_ftt + p0*CCH;
    for (int j = t; j < T1PX*CCH; j += 128) {
        int px = j >> 7, c = j & 127;
        gf[j] = sF[c*36 + px];
    }
}

// ---------------------------------------------------------------------------
// Kernel 2: local attention, SMEM-FREE windows, 2 px/warp, TILE=16,
// 512 blocks (4096 warps, ~7/SMSP). Warps independent; 1 block barrier.
// ---------------------------------------------------------------------------
__global__ void __launch_bounds__(256) attn_kernel(float* __restrict__ out)
{
    __shared__ float simw[TILE*KK];       // [16][81]
    __shared__ float pmat[8*NV*PML];      // per-warp [18][9]
    __shared__ float sout[TILE*132];      // output staging

    const int t = threadIdx.x, lane = t & 31, w = t >> 5;
    const int x0 = blockIdx.x * TILE;
    const int y  = blockIdx.y;
    const int n  = blockIdx.z;
    const int pb = w * 2;                 // 2 px per warp
    const int c4 = lane * 4;

    float* pmw = pmat + w * NV*PML;
    const int vu  = lane / 9;             // lane -> value v = u*9+dj (lane<18)
    const int vdj = lane - vu*9;
    float* simw_dst = simw + (pb + vu)*KK + vdj;   // + di*9

    const float* base = g_ftt + (size_t)n*HW*CCH;

    // query (= G@fk) vectors, packed
    ull q01[2], q23[2];
#pragma unroll
    for (int u = 0; u < 2; u++) {
        float4 q = *(const float4*)&g_qt[((n*HH + y)*WWD + x0 + pb + u)*CCH + c4];
        q01[u] = pack2(q.x, q.y);
        q23[u] = pack2(q.z, q.w);
    }

    // ================= Phase A: sim = qg . ft windows =================
#pragma unroll 1
    for (int di = 0; di < LWIN; di++) {
        const int gy = y + di - 4;
        if ((unsigned)gy < (unsigned)HH) {
            const float* rowp = base + ((size_t)gy*WWD)*CCH + c4;
#pragma unroll
            for (int jj = 0; jj < 10; jj++) {          // 2 px + 8 halo
                const int gx = x0 + pb - 4 + jj;       // warp-uniform
                float4 k4 = make_float4(0.f, 0.f, 0.f, 0.f);
                if ((unsigned)gx < (unsigned)WWD)
                    k4 = *(const float4*)&rowp[(size_t)gx*CCH];
                ull k01 = pack2(k4.x, k4.y), k23 = pack2(k4.z, k4.w);
#pragma unroll
                for (int u = 0; u < 2; u++) {
                    int dj = jj - u;
                    if (dj >= 0 && dj < 9) {
                        ull tt = fma2(q01[u], k01, 0ull);
                        tt = fma2(q23[u], k23, tt);
                        float2 p = unpack2(tt);
                        float v = p.x + p.y;
                        v += __shfl_xor_sync(0xffffffffu, v, 16);
                        v += __shfl_xor_sync(0xffffffffu, v, 8);
                        if (lane < 8) pmw[(u*9 + dj)*PML + lane] = v;
                    }
                }
            }
            __syncwarp();
            if (lane < NV) {   // final reduce: lane sums row 'lane'
                const float* r = pmw + lane*PML;
                simw_dst[di*LWIN] =
                    ((r[0]+r[1]) + (r[2]+r[3])) + ((r[4]+r[5]) + (r[6]+r[7]));
            }
            __syncwarp();
        } else {
            if (lane < NV) simw_dst[di*LWIN] = 0.f;
        }
    }
    __syncwarp();

    // ================= Phase B: softmax over 81 (own rows only) ============
#pragma unroll 1
    for (int u = 0; u < 2; u++) {
        float* srow = simw + (pb + u)*KK;
        float v0 = srow[lane];
        float v1 = srow[32 + lane];
        float v2 = (lane < 17) ? srow[64 + lane] : -1e30f;
        float m = fmaxf(fmaxf(v0, v1), v2);
        m = fmaxf(m, __shfl_xor_sync(0xffffffffu, m, 16));
        m = fmaxf(m, __shfl_xor_sync(0xffffffffu, m, 8));
        m = fmaxf(m, __shfl_xor_sync(0xffffffffu, m, 4));
        m = fmaxf(m, __shfl_xor_sync(0xffffffffu, m, 2));
        m = fmaxf(m, __shfl_xor_sync(0xffffffffu, m, 1));
        float e0 = __expf(v0 - m);
        float e1 = __expf(v1 - m);
        float e2 = (lane < 17) ? __expf(v2 - m) : 0.f;
        float s = e0 + e1 + e2;
        s += __shfl_xor_sync(0xffffffffu, s, 16);
        s += __shfl_xor_sync(0xffffffffu, s, 8);
        s += __shfl_xor_sync(0xffffffffu, s, 4);
        s += __shfl_xor_sync(0xffffffffu, s, 2);
        s += __shfl_xor_sync(0xffffffffu, s, 1);
        float inv = 1.0f / s;
        srow[lane]      = e0 * inv;
        srow[32 + lane] = e1 * inv;
        if (lane < 17) srow[64 + lane] = e2 * inv;
    }
    __syncwarp();

    // ================= Phase C: out = ft windows @ weights =================
    ull o01[2], o23[2];
#pragma unroll
    for (int u = 0; u < 2; u++) { o01[u] = 0ull; o23[u] = 0ull; }

#pragma unroll 1
    for (int di = 0; di < LWIN; di++) {
        const int gy = y + di - 4;
        if ((unsigned)gy >= (unsigned)HH) continue;
        const float* rowp = base + ((size_t)gy*WWD)*CCH + c4;
#pragma unroll
        for (int jj = 0; jj < 10; jj++) {
            const int gx = x0 + pb - 4 + jj;
            float4 f4 = make_float4(0.f, 0.f, 0.f, 0.f);
            if ((unsigned)gx < (unsigned)WWD)
                f4 = *(const float4*)&rowp[(size_t)gx*CCH];
            ull f01 = pack2(f4.x, f4.y), f23 = pack2(f4.z, f4.w);
#pragma unroll
            for (int u = 0; u < 2; u++) {
                int dj = jj - u;
                if (dj >= 0 && dj < 9) {
                    float wv = simw[(pb + u)*KK + di*LWIN + dj];  // broadcast
                    ull ww = pack2(wv, wv);
                    o01[u] = fma2(f01, ww, o01[u]);
                    o23[u] = fma2(f23, ww, o23[u]);
                }
            }
        }
    }

    // output staging + coalesced (n,c,h,w) store
#pragma unroll
    for (int u = 0; u < 2; u++) {
        float2 a = unpack2(o01[u]);
        float2 b = unpack2(o23[u]);
        *(float4*)&sout[(pb+u)*132 + c4] = make_float4(a.x, a.y, b.x, b.y);
    }
    __syncthreads();

    float* ob = out + (n*CCH*HH + y)*WWD + x0;
    for (int j = t; j < CCH*TILE; j += 256) {
        int c = j >> 4, px = j & 15;
        ob[c*HW + px] = sout[px*132 + c];
    }
}

// ---------------------------------------------------------------------------
extern "C" void kernel_launch(void* const* d_in, const int* in_sizes, int n_in,
                              void* d_out, int out_size)
{
    (void)in_sizes; (void)n_in; (void)out_size;
    const float* ft = (const float*)d_in[0];
    const float* fk = (const float*)d_in[1];
    const float* Wm = (const float*)d_in[2];
    float* out = (float*)d_out;

    const size_t smem1 = (2*CCH*36 + T1PX*129) * sizeof(float);  // ~53.4 KB
    cudaFuncSetAttribute(proj_kernel, cudaFuncAttributeMaxDynamicSharedMemorySize,
                         (int)smem1);

    gemmG_kernel<<<CCH, CCH>>>(Wm);
    proj_kernel<<<NPIX / T1PX, 128, smem1>>>(ft, fk);

    dim3 g2(WWD / TILE, HH, NB);
    attn_kernel<<<g2, 256>>>(out);
}